// round 1
// baseline (speedup 1.0000x reference)
#include <cuda_runtime.h>
#include <cstddef>

// Problem constants (from reference setup_inputs):
//   B=8, L=4096, D=512, HEAD h=16, n = L/h = 256
// Math collapses (k is all-ones => softmax over l is exactly uniform = 1/n):
//   A[b,n,h,l] = 1/256                         (q is unused)
//   V[b, n*16+h, d] = (1/256) * sum_{l=0..15} v[b, l*256+n, d]   (independent of h)
// Output = V (B*L*D = 16777216 f32) followed by A (B*n*h*n = 8388608 f32).

namespace {
constexpr int B = 8;
constexpr int L = 4096;
constexpr int D = 512;
constexpr int H = 16;
constexpr int N = 256;              // L / H
constexpr int D4 = D / 4;           // 128 float4 per row
constexpr long long V_ELEMS = (long long)B * L * D;        // 16,777,216
constexpr long long A_ELEMS = (long long)B * N * H * N;    // 8,388,608
constexpr float INV_N = 1.0f / 256.0f;
}

// One thread per (b, n, dq): reduce 16 head-blocks of v, broadcast to 16 h-slots.
__global__ void __launch_bounds__(256) v_reduce_bcast_kernel(
    const float4* __restrict__ v, float4* __restrict__ out)
{
    int idx = blockIdx.x * blockDim.x + threadIdx.x;   // 0 .. B*N*D4-1 = 262143
    int dq = idx & (D4 - 1);          // 0..127
    int n  = (idx >> 7) & (N - 1);    // 0..255
    int b  = idx >> 15;               // 0..7

    const float4* vb = v + (size_t)b * L * D4 + (size_t)n * D4 + dq;

    float4 acc = make_float4(0.f, 0.f, 0.f, 0.f);
    #pragma unroll
    for (int l = 0; l < H; ++l) {
        float4 t = vb[(size_t)l * N * D4];
        acc.x += t.x; acc.y += t.y; acc.z += t.z; acc.w += t.w;
    }
    acc.x *= INV_N; acc.y *= INV_N; acc.z *= INV_N; acc.w *= INV_N;

    float4* ob = out + (size_t)b * L * D4 + (size_t)(n * H) * D4 + dq;
    #pragma unroll
    for (int h = 0; h < H; ++h) {
        ob[(size_t)h * D4] = acc;
    }
}

// Fill A with the constant 1/256 (vectorized).
__global__ void __launch_bounds__(256) a_fill_kernel(float4* __restrict__ a, long long n4)
{
    long long i = (long long)blockIdx.x * blockDim.x + threadIdx.x;
    if (i < n4) {
        a[i] = make_float4(INV_N, INV_N, INV_N, INV_N);
    }
}

extern "C" void kernel_launch(void* const* d_in, const int* in_sizes, int n_in,
                              void* d_out, int out_size)
{
    // Inputs: d_in[0] = q (unused — mathematically irrelevant), d_in[1] = v.
    const float4* v = (const float4*)d_in[1];
    float* out = (float*)d_out;

    // V kernel: 262144 threads
    {
        int total = B * N * D4;           // 262144
        int tpb = 256;
        v_reduce_bcast_kernel<<<total / tpb, tpb>>>(v, (float4*)out);
    }

    // A fill (if present in the output buffer)
    if ((long long)out_size >= V_ELEMS + A_ELEMS) {
        long long n4 = A_ELEMS / 4;       // 2,097,152
        int tpb = 256;
        long long blocks = (n4 + tpb - 1) / tpb;
        a_fill_kernel<<<(unsigned)blocks, tpb>>>((float4*)(out + V_ELEMS), n4);
    }
}

// round 2
// speedup vs baseline: 1.0587x; 1.0587x over previous
#include <cuda_runtime.h>
#include <cstddef>

// Problem constants (from reference setup_inputs):
//   B=8, L=4096, D=512, HEAD h=16, n = L/h = 256
// Math collapses (k is all-ones => softmax over l is exactly uniform = 1/n):
//   A[b,n,h,l] = 1/256                        (q is unused)
//   V[b, n*16+h, d] = (1/256) * sum_{l=0..15} v[b, l*256+n, d]   (independent of h)
// Output = V (16,777,216 f32) followed by A (8,388,608 f32).

namespace {
constexpr int B = 8;
constexpr int L = 4096;
constexpr int D = 512;
constexpr int H = 16;
constexpr int N = 256;              // L / H
constexpr int D4 = D / 4;           // 128 float4 per row
constexpr long long V_ELEMS = (long long)B * L * D;        // 16,777,216
constexpr long long A_ELEMS = (long long)B * N * H * N;    // 8,388,608
constexpr float INV_N = 1.0f / 256.0f;

constexpr int TPB = 256;
constexpr int V_BLOCKS = (B * N * D4) / TPB;               // 1024
constexpr long long A_F4 = A_ELEMS / 4;                    // 2,097,152 float4
constexpr int FILL_PER_THREAD = 8;                         // 8 x float4 = 128B / thread
constexpr int A_BLOCKS = (int)(A_F4 / (TPB * FILL_PER_THREAD)); // 1024
}

// Fused kernel: blocks [0, V_BLOCKS) do the V reduce+broadcast,
// blocks [V_BLOCKS, V_BLOCKS+A_BLOCKS) fill A with 1/256.
__global__ void __launch_bounds__(TPB) fused_kernel(
    const float4* __restrict__ v, float4* __restrict__ out)
{
    int blk = blockIdx.x;
    if (blk < V_BLOCKS) {
        // ---- V: one thread per (b, n, dq) ----
        int idx = blk * TPB + threadIdx.x;    // 0 .. 262143
        int dq = idx & (D4 - 1);              // 0..127
        int n  = (idx >> 7) & (N - 1);        // 0..255
        int b  = idx >> 15;                   // 0..7

        const float4* vb = v + (size_t)b * L * D4 + (size_t)n * D4 + dq;

        float4 acc = make_float4(0.f, 0.f, 0.f, 0.f);
        #pragma unroll
        for (int l = 0; l < H; ++l) {
            float4 t = vb[(size_t)l * N * D4];
            acc.x += t.x; acc.y += t.y; acc.z += t.z; acc.w += t.w;
        }
        acc.x *= INV_N; acc.y *= INV_N; acc.z *= INV_N; acc.w *= INV_N;

        float4* ob = out + (size_t)b * L * D4 + (size_t)(n * H) * D4 + dq;
        #pragma unroll
        for (int h = 0; h < H; ++h) {
            ob[(size_t)h * D4] = acc;
        }
    } else {
        // ---- A fill: 8 coalesced float4 stores per thread ----
        float4* a = out + (V_ELEMS / 4);
        const float4 c = make_float4(INV_N, INV_N, INV_N, INV_N);
        long long base = (long long)(blk - V_BLOCKS) * TPB * FILL_PER_THREAD
                       + threadIdx.x;
        #pragma unroll
        for (int k = 0; k < FILL_PER_THREAD; ++k) {
            a[base + (long long)k * TPB] = c;
        }
    }
}

extern "C" void kernel_launch(void* const* d_in, const int* in_sizes, int n_in,
                              void* d_out, int out_size)
{
    // Inputs: d_in[0] = q (mathematically irrelevant), d_in[1] = v.
    const float4* v = (const float4*)d_in[1];
    float4* out = (float4*)d_out;

    bool has_a = ((long long)out_size >= V_ELEMS + A_ELEMS);
    int grid = V_BLOCKS + (has_a ? A_BLOCKS : 0);   // 2048
    fused_kernel<<<grid, TPB>>>(v, out);
}